// round 1
// baseline (speedup 1.0000x reference)
#include <cuda_runtime.h>
#include <cstdint>
#include <math.h>

#define T_TOK 4096
#define EMB   1024
#define HID   2816
#define NE    8
#define NPAIR (T_TOK * 2)

// ---------------- device scratch (static globals; no runtime alloc) ----------
__device__ int   g_counts[NE];
__device__ int   g_offsets[NE + 1];
__device__ int   g_cursor[NE];
__device__ int   g_tok_e[T_TOK][2];
__device__ float g_tok_p[T_TOK][2];
__device__ int   g_pair_token[NPAIR];
__device__ float g_pair_gate[NPAIR];
__device__ int   g_pair_slot[NPAIR];
__device__ float g_hbuf[(size_t)NPAIR * HID];        // 92 MB
__device__ float g_contrib[2][T_TOK][EMB];           // 32 MB

// ---------------- helpers ----------------------------------------------------
__device__ __forceinline__ float to_tf32(float x) {
    uint32_t u;
    asm("cvt.rna.tf32.f32 %0, %1;" : "=r"(u) : "f"(x));
    return __uint_as_float(u);
}

__device__ __forceinline__ void mma_tf32(float c[4], const uint32_t a[4], const uint32_t b[2]) {
    asm volatile(
        "mma.sync.aligned.m16n8k8.row.col.f32.tf32.tf32.f32 "
        "{%0,%1,%2,%3}, {%4,%5,%6,%7}, {%8,%9}, {%0,%1,%2,%3};\n"
        : "+f"(c[0]), "+f"(c[1]), "+f"(c[2]), "+f"(c[3])
        : "r"(a[0]), "r"(a[1]), "r"(a[2]), "r"(a[3]),
          "r"(b[0]), "r"(b[1]));
}

// ---------------- kernel 0: zero metadata -----------------------------------
__global__ void init_kernel() {
    int i = threadIdx.x;
    if (i < NE) { g_counts[i] = 0; g_cursor[i] = 0; }
}

// ---------------- kernel 1: router (one warp per token) ----------------------
__global__ void router_kernel(const float* __restrict__ x, const float* __restrict__ wr) {
    int gw   = (blockIdx.x * blockDim.x + threadIdx.x) >> 5;
    int lane = threadIdx.x & 31;
    if (gw >= T_TOK) return;
    const float* xr = x + (size_t)gw * EMB;
    float acc[NE];
#pragma unroll
    for (int e = 0; e < NE; e++) acc[e] = 0.f;
    for (int k = lane; k < EMB; k += 32) {
        float  xv = xr[k];
        float4 wa = *(const float4*)(wr + k * NE);
        float4 wb = *(const float4*)(wr + k * NE + 4);
        acc[0] += xv * wa.x; acc[1] += xv * wa.y; acc[2] += xv * wa.z; acc[3] += xv * wa.w;
        acc[4] += xv * wb.x; acc[5] += xv * wb.y; acc[6] += xv * wb.z; acc[7] += xv * wb.w;
    }
#pragma unroll
    for (int e = 0; e < NE; e++)
#pragma unroll
        for (int o = 16; o > 0; o >>= 1) acc[e] += __shfl_xor_sync(0xffffffffu, acc[e], o);
    if (lane == 0) {
        int i0 = 0; float v0 = acc[0];
#pragma unroll
        for (int e = 1; e < NE; e++) if (acc[e] > v0) { v0 = acc[e]; i0 = e; }
        int i1 = -1; float v1 = -1e30f;
#pragma unroll
        for (int e = 0; e < NE; e++) if (e != i0 && acc[e] > v1) { v1 = acc[e]; i1 = e; }
        float p1 = 1.f / (1.f + expf(v0 - v1));
        float p0 = 1.f - p1;
        g_tok_e[gw][0] = i0; g_tok_e[gw][1] = i1;
        g_tok_p[gw][0] = p0; g_tok_p[gw][1] = p1;
        atomicAdd(&g_counts[i0], 1);
        atomicAdd(&g_counts[i1], 1);
    }
}

// ---------------- kernel 2: prefix sum over 8 experts ------------------------
__global__ void offsets_kernel() {
    if (threadIdx.x == 0) {
        int s = 0;
        for (int e = 0; e < NE; e++) { g_offsets[e] = s; s += g_counts[e]; }
        g_offsets[NE] = s;
    }
}

// ---------------- kernel 3: scatter pairs into compact per-expert lists ------
__global__ void scatter_kernel() {
    int i = blockIdx.x * blockDim.x + threadIdx.x;
    if (i >= NPAIR) return;
    int t = i >> 1, k = i & 1;
    int e = g_tok_e[t][k];
    int pos = g_offsets[e] + atomicAdd(&g_cursor[e], 1);
    g_pair_token[pos] = t;
    g_pair_gate[pos]  = g_tok_p[t][k];
    g_pair_slot[pos]  = k;
}

// ---------------- kernel 4: phase-1 grouped GEMM + SwiGLU --------------------
// CTA: 128 pairs x 64 hid cols, two B matrices (w1, w3); K = 1024.
#define BM  128
#define BN1 64
#define BK  32
#define APAD 12   /* stride 44 floats: float4-aligned AND conflict-free frag loads */

__global__ void __launch_bounds__(256) ffn1_kernel(const float* __restrict__ x,
                                                   const float* __restrict__ w1,
                                                   const float* __restrict__ w3) {
    int e = blockIdx.z, mt = blockIdx.y, nt = blockIdx.x;
    int pbeg = g_offsets[e], pend = g_offsets[e + 1];
    int m0 = pbeg + mt * BM;
    if (m0 >= pend) return;
    int mcnt = pend - m0; if (mcnt > BM) mcnt = BM;

    __shared__ float As[BM][BK + APAD];
    __shared__ float B1s[BK][BN1 + 8];   // stride 72 floats
    __shared__ float B3s[BK][BN1 + 8];
    __shared__ int   rowtok[BM];

    int tid = threadIdx.x;
    if (tid < BM) rowtok[tid] = (tid < mcnt) ? g_pair_token[m0 + tid] : -1;
    __syncthreads();

    int warp = tid >> 5, lane = tid & 31;
    int wm = warp & 3, wn = warp >> 2;      // 4x2 warp grid; warp tile 32x32

    float ch[2][4][4], cg[2][4][4];
#pragma unroll
    for (int a = 0; a < 2; a++)
#pragma unroll
        for (int b = 0; b < 4; b++)
#pragma unroll
            for (int c = 0; c < 4; c++) { ch[a][b][c] = 0.f; cg[a][b][c] = 0.f; }

    const float* w1p = w1 + (size_t)e * EMB * HID + (size_t)nt * BN1;
    const float* w3p = w3 + (size_t)e * EMB * HID + (size_t)nt * BN1;

    int arow = tid >> 1;
    int atok = rowtok[arow];
    const float4* asrc = (atok >= 0) ? (const float4*)(x + (size_t)atok * EMB) : nullptr;
    int ac4 = (tid & 1) * 4;

    for (int k0 = 0; k0 < EMB; k0 += BK) {
        // load A tile (gathered token rows)
#pragma unroll
        for (int i = 0; i < 4; i++) {
            float4 v = asrc ? asrc[(k0 >> 2) + ac4 + i] : make_float4(0.f, 0.f, 0.f, 0.f);
            float4 t = make_float4(to_tf32(v.x), to_tf32(v.y), to_tf32(v.z), to_tf32(v.w));
            *(float4*)&As[arow][(ac4 + i) << 2] = t;
        }
        // load B tiles (w1, w3): 32 x 64 each = 512 float4
#pragma unroll
        for (int j = 0; j < 2; j++) {
            int idx = tid + j * 256;
            int r = idx >> 4, c4 = idx & 15;
            float4 v1 = *(const float4*)(w1p + (size_t)(k0 + r) * HID + c4 * 4);
            float4 v3 = *(const float4*)(w3p + (size_t)(k0 + r) * HID + c4 * 4);
            *(float4*)&B1s[r][c4 * 4] = make_float4(to_tf32(v1.x), to_tf32(v1.y), to_tf32(v1.z), to_tf32(v1.w));
            *(float4*)&B3s[r][c4 * 4] = make_float4(to_tf32(v3.x), to_tf32(v3.y), to_tf32(v3.z), to_tf32(v3.w));
        }
        __syncthreads();
#pragma unroll
        for (int kk = 0; kk < BK; kk += 8) {
            uint32_t a[2][4];
            int ar = wm * 32 + (lane >> 2);
            int acl = kk + (lane & 3);
#pragma unroll
            for (int mi = 0; mi < 2; mi++) {
                a[mi][0] = __float_as_uint(As[ar + mi * 16][acl]);
                a[mi][1] = __float_as_uint(As[ar + mi * 16 + 8][acl]);
                a[mi][2] = __float_as_uint(As[ar + mi * 16][acl + 4]);
                a[mi][3] = __float_as_uint(As[ar + mi * 16 + 8][acl + 4]);
            }
            int bk = kk + (lane & 3);
            int bnb = wn * 32 + (lane >> 2);
#pragma unroll
            for (int ni = 0; ni < 4; ni++) {
                uint32_t b1[2], b3[2];
                b1[0] = __float_as_uint(B1s[bk][bnb + ni * 8]);
                b1[1] = __float_as_uint(B1s[bk + 4][bnb + ni * 8]);
                b3[0] = __float_as_uint(B3s[bk][bnb + ni * 8]);
                b3[1] = __float_as_uint(B3s[bk + 4][bnb + ni * 8]);
#pragma unroll
                for (int mi = 0; mi < 2; mi++) {
                    mma_tf32(ch[mi][ni], a[mi], b1);
                    mma_tf32(cg[mi][ni], a[mi], b3);
                }
            }
        }
        __syncthreads();
    }
    // epilogue: silu(h) * g -> scratch
#pragma unroll
    for (int mi = 0; mi < 2; mi++)
#pragma unroll
        for (int ni = 0; ni < 4; ni++)
#pragma unroll
            for (int r = 0; r < 4; r++) {
                int row = wm * 32 + mi * 16 + (lane >> 2) + ((r >= 2) ? 8 : 0);
                int col = wn * 32 + ni * 8 + (lane & 3) * 2 + (r & 1);
                if (row < mcnt) {
                    float h = ch[mi][ni][r], g = cg[mi][ni][r];
                    float val = (h / (1.f + expf(-h))) * g;
                    g_hbuf[(size_t)(m0 + row) * HID + nt * BN1 + col] = val;
                }
            }
}

// ---------------- kernel 5: phase-2 grouped GEMM (h @ w2) * gate -------------
#define BN2 128

__global__ void __launch_bounds__(256) ffn2_kernel(const float* __restrict__ w2) {
    int e = blockIdx.z, mt = blockIdx.y, nt = blockIdx.x;
    int pbeg = g_offsets[e], pend = g_offsets[e + 1];
    int m0 = pbeg + mt * BM;
    if (m0 >= pend) return;
    int mcnt = pend - m0; if (mcnt > BM) mcnt = BM;

    __shared__ float As[BM][BK + APAD];
    __shared__ float Bs[BK][BN2 + 8];    // stride 136 floats
    __shared__ int   stok[BM];
    __shared__ float sgate[BM];
    __shared__ int   sslot[BM];

    int tid = threadIdx.x;
    if (tid < BM) {
        bool v = tid < mcnt;
        int p = m0 + tid;
        stok[tid]  = v ? g_pair_token[p] : 0;
        sgate[tid] = v ? g_pair_gate[p] : 0.f;
        sslot[tid] = v ? g_pair_slot[p] : 0;
    }
    __syncthreads();

    int warp = tid >> 5, lane = tid & 31;
    int wm = warp & 3, wn = warp >> 2;     // warp tile 32 rows x 64 cols

    float acc[2][8][4];
#pragma unroll
    for (int a = 0; a < 2; a++)
#pragma unroll
        for (int b = 0; b < 8; b++)
#pragma unroll
            for (int c = 0; c < 4; c++) acc[a][b][c] = 0.f;

    const float* w2p = w2 + (size_t)e * HID * EMB + (size_t)nt * BN2;

    int arow = tid >> 1;
    int ac4 = (tid & 1) * 4;
    const float4* asrc = (arow < mcnt) ? (const float4*)(g_hbuf + (size_t)(m0 + arow) * HID) : nullptr;

    for (int k0 = 0; k0 < HID; k0 += BK) {
#pragma unroll
        for (int i = 0; i < 4; i++) {
            float4 v = asrc ? asrc[(k0 >> 2) + ac4 + i] : make_float4(0.f, 0.f, 0.f, 0.f);
            float4 t = make_float4(to_tf32(v.x), to_tf32(v.y), to_tf32(v.z), to_tf32(v.w));
            *(float4*)&As[arow][(ac4 + i) << 2] = t;
        }
        // B tile: 32 x 128 = 1024 float4
#pragma unroll
        for (int j = 0; j < 4; j++) {
            int idx = tid + j * 256;
            int r = idx >> 5, c4 = idx & 31;
            float4 v = *(const float4*)(w2p + (size_t)(k0 + r) * EMB + c4 * 4);
            *(float4*)&Bs[r][c4 * 4] = make_float4(to_tf32(v.x), to_tf32(v.y), to_tf32(v.z), to_tf32(v.w));
        }
        __syncthreads();
#pragma unroll
        for (int kk = 0; kk < BK; kk += 8) {
            uint32_t a[2][4];
            int ar = wm * 32 + (lane >> 2);
            int acl = kk + (lane & 3);
#pragma unroll
            for (int mi = 0; mi < 2; mi++) {
                a[mi][0] = __float_as_uint(As[ar + mi * 16][acl]);
                a[mi][1] = __float_as_uint(As[ar + mi * 16 + 8][acl]);
                a[mi][2] = __float_as_uint(As[ar + mi * 16][acl + 4]);
                a[mi][3] = __float_as_uint(As[ar + mi * 16 + 8][acl + 4]);
            }
            int bk = kk + (lane & 3);
            int bnb = wn * 64 + (lane >> 2);
#pragma unroll
            for (int ni = 0; ni < 8; ni++) {
                uint32_t b[2];
                b[0] = __float_as_uint(Bs[bk][bnb + ni * 8]);
                b[1] = __float_as_uint(Bs[bk + 4][bnb + ni * 8]);
#pragma unroll
                for (int mi = 0; mi < 2; mi++) mma_tf32(acc[mi][ni], a[mi], b);
            }
        }
        __syncthreads();
    }
    // epilogue: gate * acc -> per-slot contribution buffer (race-free)
#pragma unroll
    for (int mi = 0; mi < 2; mi++)
#pragma unroll
        for (int ni = 0; ni < 8; ni++)
#pragma unroll
            for (int r = 0; r < 4; r++) {
                int row = wm * 32 + mi * 16 + (lane >> 2) + ((r >= 2) ? 8 : 0);
                int col = wn * 64 + ni * 8 + (lane & 3) * 2 + (r & 1);
                if (row < mcnt) {
                    int t = stok[row];
                    g_contrib[sslot[row]][t][nt * BN2 + col] = sgate[row] * acc[mi][ni][r];
                }
            }
}

// ---------------- kernel 6: sum the two expert contributions -----------------
__global__ void reduce_kernel(float* __restrict__ out) {
    size_t i = (size_t)blockIdx.x * blockDim.x + threadIdx.x;
    size_t n = (size_t)T_TOK * EMB / 4;
    if (i >= n) return;
    const float4* c0 = (const float4*)&g_contrib[0][0][0];
    const float4* c1 = (const float4*)&g_contrib[1][0][0];
    float4 a = c0[i], b = c1[i];
    ((float4*)out)[i] = make_float4(a.x + b.x, a.y + b.y, a.z + b.z, a.w + b.w);
}

// ---------------- launch ------------------------------------------------------
extern "C" void kernel_launch(void* const* d_in, const int* in_sizes, int n_in,
                              void* d_out, int out_size) {
    const float* x  = (const float*)d_in[0];
    const float* wr = (const float*)d_in[1];
    const float* w1 = (const float*)d_in[2];
    const float* w3 = (const float*)d_in[3];
    const float* w2 = (const float*)d_in[4];
    float* out = (float*)d_out;

    init_kernel<<<1, 32>>>();
    router_kernel<<<(T_TOK * 32 + 255) / 256, 256>>>(x, wr);
    offsets_kernel<<<1, 32>>>();
    scatter_kernel<<<(NPAIR + 255) / 256, 256>>>();

    dim3 g1(HID / BN1, (T_TOK + BM - 1) / BM, NE);   // 44 x 32 x 8, most M-tiles exit early
    ffn1_kernel<<<g1, 256>>>(x, w1, w3);

    dim3 g2(EMB / BN2, (T_TOK + BM - 1) / BM, NE);   // 8 x 32 x 8
    ffn2_kernel<<<g2, 256>>>(w2);

    reduce_kernel<<<((T_TOK * EMB / 4) + 255) / 256, 256>>>(out);
}